// round 13
// baseline (speedup 1.0000x reference)
#include <cuda_runtime.h>
#include <cuda_fp16.h>
#include <cstdint>

// ---------------- problem constants ----------------
#define Hc      2048
#define Mslots  256
#define Bc      8
#define Sc      4096
#define NROWS   (Bc * Sc)        // 32768
#define BRr     64               // rows per CTA
#define THREADS 256              // 8 warps; 2 CTAs/SM
#define NCTA    (NROWS / BRr)    // 512

// ---------------- dynamic smem layout (92KB) ----------------
// double-buffered phase-1 staging:
#define BUFSZ  40960             // per buffer: XA(8KB) + MB(32KB)
#define XA_F16 0                 // x fp16   [64 x 64k]   (within buffer)
#define MB_F16 8192              // mem fp16 [256 x 64k]  (within buffer)
#define MSUM   81920             // fp32 [2048] per-CTA column sums (8KB)
#define MSW    90112             // fp32 [2][8][64] per-warp partials (4KB)
#define DSMEM  94208
// logits scratch (after phase 1; aliases staging buffers):
#define LG_OFF 0                 // fp32 [64 rows][256]  64KB
#define LG_STR 256

#define SWZ128(o) ((o) ^ (((o) >> 3) & 0x70))

// ---------------- scratch (__device__ globals) ----------------
__device__ __align__(16) __half g_memF[Mslots * Hc];     // mem fp16 [slot][k]
__device__ __align__(16) float  g_part2[NCTA * Hc];      // per-CTA column sums (4MB)
__device__ __align__(16) float  g_xmean[Bc * Hc];
__device__ __align__(16) float  g_wc[Bc * Hc];

// ---------------- helpers ----------------
__device__ __forceinline__ uint32_t smem_u32(const void* p) {
    uint32_t a;
    asm("{ .reg .u64 t; cvta.to.shared.u64 t, %1; cvt.u32.u64 %0, t; }" : "=r"(a) : "l"(p));
    return a;
}
__device__ __forceinline__ void ldsm_x4(uint32_t (&r)[4], uint32_t addr) {
    asm volatile("ldmatrix.sync.aligned.m8n8.x4.shared.b16 {%0,%1,%2,%3}, [%4];"
                 : "=r"(r[0]), "=r"(r[1]), "=r"(r[2]), "=r"(r[3]) : "r"(addr));
}
__device__ __forceinline__ void mma_f16(float (&c)[4], const uint32_t (&a)[4],
                                        uint32_t b0, uint32_t b1) {
    asm volatile(
        "mma.sync.aligned.m16n8k16.row.col.f32.f16.f16.f32 "
        "{%0,%1,%2,%3}, {%4,%5,%6,%7}, {%8,%9}, {%0,%1,%2,%3};"
        : "+f"(c[0]), "+f"(c[1]), "+f"(c[2]), "+f"(c[3])
        : "r"(a[0]), "r"(a[1]), "r"(a[2]), "r"(a[3]), "r"(b0), "r"(b1));
}

// ======================= prep: mem -> fp16 =======================
__global__ void prep_mem_kernel(const float* __restrict__ mem) {
    int i = blockIdx.x * 256 + threadIdx.x;
    g_memF[i] = __float2half_rn(mem[i]);
}

// ======================= fused kernel =======================
extern __shared__ __align__(1024) char dsm[];

__global__ __launch_bounds__(THREADS, 2)
void fused_mma_kernel(const float* __restrict__ x,
                      const float* __restrict__ memf,
                      float* __restrict__ comb,
                      float* __restrict__ readm) {
    const int tid = threadIdx.x;
    const int lane = tid & 31;
    const int wid = tid >> 5;
    const int wm = wid >> 2;             // 0..1 (M position)
    const int wn = wid & 3;              // 0..3 (N position)
    const int row0 = blockIdx.x * BRr;
    const uint32_t sb = smem_u32(dsm);
    const int b_nfp = (lane >> 4) & 1;
    const int b_kh  = (lane >> 3) & 1;
    const int b_row = lane & 7;

    float* msum = (float*)(dsm + MSUM);
    float* msw  = (float*)(dsm + MSW);

    // stage chunk t into buffer (t&1): x fp16 (+ comb copy + mean partials), mem fp16
    auto stage = [&](int t) {
        const int k0 = t * 64;
        char* buf = dsm + (size_t)(t & 1) * BUFSZ;
        float4 ps = make_float4(0.f, 0.f, 0.f, 0.f);
#pragma unroll
        for (int it = 0; it < 4; ++it) {
            int idx = it * 256 + tid;
            int r = idx >> 4, c4 = idx & 15;
            float4 v = *(const float4*)(x + (size_t)(row0 + r) * Hc + k0 + c4 * 4);
            *(float4*)(comb + (size_t)(row0 + r) * (2 * Hc) + k0 + c4 * 4) = v;
            ps.x += v.x; ps.y += v.y; ps.z += v.z; ps.w += v.w;
            __half2 h0 = __floats2half2_rn(v.x, v.y);
            __half2 h1 = __floats2half2_rn(v.z, v.w);
            uint32_t off = SWZ128((uint32_t)(r * 128 + c4 * 8));
            *(uint2*)(buf + XA_F16 + off) =
                make_uint2(*reinterpret_cast<uint32_t*>(&h0), *reinterpret_cast<uint32_t*>(&h1));
        }
#pragma unroll
        for (int it = 0; it < 8; ++it) {
            int idx = it * 256 + tid;
            int m = idx >> 3, c8 = idx & 7;
            uint32_t off = SWZ128((uint32_t)(m * 128 + c8 * 16));
            *(uint4*)(buf + MB_F16 + off) = *(const uint4*)(g_memF + (size_t)m * Hc + k0 + c8 * 8);
        }
        // fold row-pairs (lanes l and l^16 share the same column group c4 = lane&15)
        ps.x += __shfl_xor_sync(0xffffffffu, ps.x, 16);
        ps.y += __shfl_xor_sync(0xffffffffu, ps.y, 16);
        ps.z += __shfl_xor_sync(0xffffffffu, ps.z, 16);
        ps.w += __shfl_xor_sync(0xffffffffu, ps.w, 16);
        if (lane < 16)
            *(float4*)(msw + (t & 1) * 512 + wid * 64 + lane * 4) = ps;
    };

    // ---------------- phase 1: coarse scores = x @ mem^T (fp16, double-buffered) ----------------
    float acc[2][8][4];
#pragma unroll
    for (int mf = 0; mf < 2; ++mf)
#pragma unroll
        for (int nf = 0; nf < 8; ++nf)
#pragma unroll
            for (int e = 0; e < 4; ++e) acc[mf][nf][e] = 0.f;

    stage(0);
    __syncthreads();

    for (int t = 0; t < 32; ++t) {
        if (t < 31) stage(t + 1);           // global loads issue early (other buffer)
        // fold chunk t's per-warp mean partials (written in prev iter, synced)
        if (tid < 64) {
            const float* mw = msw + (t & 1) * 512;
            float s = 0.f;
#pragma unroll
            for (int w = 0; w < 8; ++w) s += mw[w * 64 + tid];
            msum[t * 64 + tid] = s;
        }
        // compute chunk t
        const uint32_t bo = sb + (uint32_t)(t & 1) * BUFSZ;
#pragma unroll
        for (int ks = 0; ks < 4; ++ks) {
            const uint32_t kb = (uint32_t)ks * 32;
            uint32_t af[2][4];
#pragma unroll
            for (int mf = 0; mf < 2; ++mf) {
                int row = wm * 32 + mf * 16 + (lane & 15);
                uint32_t ao = SWZ128((uint32_t)(row * 128) + kb + ((uint32_t)(lane >> 4) << 4));
                ldsm_x4(af[mf], bo + XA_F16 + ao);
            }
#pragma unroll
            for (int nf2 = 0; nf2 < 4; ++nf2) {
                int slot = wn * 64 + nf2 * 16 + b_nfp * 8 + b_row;
                uint32_t bofs = SWZ128((uint32_t)(slot * 128) + kb + ((uint32_t)b_kh << 4));
                uint32_t b4[4];
                ldsm_x4(b4, bo + MB_F16 + bofs);
#pragma unroll
                for (int h = 0; h < 2; ++h) {
                    const int nf = nf2 * 2 + h;
#pragma unroll
                    for (int mf = 0; mf < 2; ++mf)
                        mma_f16(acc[mf][nf], af[mf], b4[2 * h], b4[2 * h + 1]);
                }
            }
        }
        __syncthreads();
    }

    // ---------------- flush per-CTA column sums ----------------
    for (int i = tid; i < Hc; i += THREADS)
        g_part2[(size_t)blockIdx.x * Hc + i] = msum[i];

    // ---------------- dump coarse logits (fp32) to smem ----------------
    float* lg = (float*)(dsm + LG_OFF);
#pragma unroll
    for (int mf = 0; mf < 2; ++mf)
#pragma unroll
        for (int rh = 0; rh < 2; ++rh) {
            int rloc = wm * 32 + mf * 16 + (lane >> 2) + rh * 8;
#pragma unroll
            for (int nf = 0; nf < 8; ++nf) {
                int col = wn * 64 + nf * 8 + (lane & 3) * 2;
                *(float2*)(lg + rloc * LG_STR + col) =
                    make_float2(acc[mf][nf][rh * 2], acc[mf][nf][rh * 2 + 1]);
            }
        }
    __syncthreads();

    // ---------------- per-row: refine -> softmax -> sparse-exact output ----------------
    for (int rr = 0; rr < 8; ++rr) {
        const int rl = wid * 8 + rr;
        float* Lrow = lg + rl * LG_STR;

        // coarse max
        float cm = -3.4e38f;
#pragma unroll
        for (int i = 0; i < 8; ++i) cm = fmaxf(cm, Lrow[lane + i * 32]);
#pragma unroll
        for (int d = 16; d >= 1; d >>= 1)
            cm = fmaxf(cm, __shfl_xor_sync(0xffffffffu, cm, d));
        const float thr = cm - 14.0f;

        // exact recompute of candidate slots (fp32 from global)
#pragma unroll
        for (int i = 0; i < 8; ++i) {
            int slot = lane + i * 32;
            bool cand = Lrow[slot] > thr;
            unsigned mask = __ballot_sync(0xffffffffu, cand);
            while (mask) {
                int src = __ffs(mask) - 1;
                mask &= mask - 1;
                int s2 = src + i * 32;
                const float4* xp = (const float4*)(x + (size_t)(row0 + rl) * Hc);
                const float4* mp = (const float4*)(memf + (size_t)s2 * Hc);
                float d = 0.f;
                for (int k = lane; k < Hc / 4; k += 32) {
                    float4 a = xp[k], b = mp[k];
                    d += a.x * b.x + a.y * b.y + a.z * b.z + a.w * b.w;
                }
#pragma unroll
                for (int dd = 16; dd >= 1; dd >>= 1)
                    d += __shfl_xor_sync(0xffffffffu, d, dd);
                if (lane == 0) Lrow[s2] = d;
            }
        }
        __syncwarp();

        // exact max + sum over all 256 (refined where it matters)
        float m2 = -3.4e38f;
#pragma unroll
        for (int i = 0; i < 8; ++i) m2 = fmaxf(m2, Lrow[lane + i * 32]);
#pragma unroll
        for (int d = 16; d >= 1; d >>= 1)
            m2 = fmaxf(m2, __shfl_xor_sync(0xffffffffu, m2, d));
        float s = 0.f;
#pragma unroll
        for (int i = 0; i < 8; ++i) s += __expf(Lrow[lane + i * 32] - m2);
#pragma unroll
        for (int d = 16; d >= 1; d >>= 1)
            s += __shfl_xor_sync(0xffffffffu, s, d);
        const float inv = 1.0f / s;
        const float thr2 = m2 - 14.0f;

        // output: read[rl][:] = sum_{cand} w_c * mem[c][:]  (fp32 exact, 4 h-chunks)
        float* rp = readm + (size_t)(row0 + rl) * Hc;
        float* cp = comb + (size_t)(row0 + rl) * (2 * Hc) + Hc;
#pragma unroll
        for (int hc = 0; hc < 4; ++hc) {
            float4 out[4];
#pragma unroll
            for (int j = 0; j < 4; ++j) out[j] = make_float4(0.f, 0.f, 0.f, 0.f);
#pragma unroll
            for (int i = 0; i < 8; ++i) {
                bool cand = Lrow[lane + i * 32] > thr2;
                unsigned mask = __ballot_sync(0xffffffffu, cand);
                while (mask) {
                    int src = __ffs(mask) - 1;
                    mask &= mask - 1;
                    int s2 = src + i * 32;
                    float w = __expf(Lrow[s2] - m2) * inv;
                    const float4* mp = (const float4*)(memf + (size_t)s2 * Hc) + hc * 128;
#pragma unroll
                    for (int j = 0; j < 4; ++j) {
                        float4 mv = mp[lane + j * 32];
                        out[j].x += w * mv.x;
                        out[j].y += w * mv.y;
                        out[j].z += w * mv.z;
                        out[j].w += w * mv.w;
                    }
                }
            }
#pragma unroll
            for (int j = 0; j < 4; ++j) {
                int h4 = hc * 128 + lane + j * 32;
                *(float4*)(rp + h4 * 4) = out[j];
                *(float4*)(cp + h4 * 4) = out[j];
            }
        }
    }
}

// ======================= write path =======================
__global__ void mean_reduce2_kernel() {
    const int i = blockIdx.x * 256 + threadIdx.x;   // 0 .. Bc*Hc-1
    const int b = i >> 11, col = i & (Hc - 1);
    float s = 0.f;
    const int c0 = b * (NCTA / Bc);                 // 64 CTAs per batch
    for (int j = 0; j < NCTA / Bc; ++j)
        s += g_part2[(size_t)(c0 + j) * Hc + col];
    g_xmean[i] = s * (1.0f / (float)Sc);
}

__global__ void wc_kernel(const float* __restrict__ W, const float* __restrict__ bw) {
    const int gw = (blockIdx.x * blockDim.x + threadIdx.x) >> 5;
    const int lane = threadIdx.x & 31;
    if (gw >= Bc * Hc) return;
    const int b = gw >> 11, i = gw & (Hc - 1);
    const float4* wr = (const float4*)(W + (size_t)i * Hc);
    const float4* xm = (const float4*)(g_xmean + (size_t)b * Hc);
    float s = 0.f;
    for (int k = lane; k < Hc / 4; k += 32) {
        float4 w4 = wr[k], x4 = xm[k];
        s += w4.x * x4.x + w4.y * x4.y + w4.z * x4.z + w4.w * x4.w;
    }
#pragma unroll
    for (int d = 16; d >= 1; d >>= 1) s += __shfl_xor_sync(0xffffffffu, s, d);
    if (lane == 0) g_wc[gw] = s + bw[i];
}

__global__ void newmem_kernel(const float* __restrict__ mem, float* __restrict__ outnm) {
    const size_t idx = (size_t)blockIdx.x * 256 + threadIdx.x;
    const int h4 = (int)(idx & (Hc / 4 - 1));
    const size_t rest = idx >> 9;
    const int m = (int)(rest & (Mslots - 1));
    const int b = (int)(rest >> 8);
    float4 mv = *(const float4*)(mem + (size_t)m * Hc + h4 * 4);
    float4 wv = *(const float4*)(g_wc + (size_t)b * Hc + h4 * 4);
    ((float4*)outnm)[idx] = make_float4(0.9f * mv.x + 0.1f * wv.x, 0.9f * mv.y + 0.1f * wv.y,
                                        0.9f * mv.z + 0.1f * wv.z, 0.9f * mv.w + 0.1f * wv.w);
}

// ======================= launch =======================
extern "C" void kernel_launch(void* const* d_in, const int* in_sizes, int n_in,
                              void* d_out, int out_size) {
    const float* x   = (const float*)d_in[0];
    const float* mem = (const float*)d_in[1];
    const float* W   = (const float*)d_in[2];
    const float* bw  = (const float*)d_in[3];

    float* comb  = (float*)d_out;
    float* readm = comb + (size_t)NROWS * 2 * Hc;
    float* newm  = readm + (size_t)NROWS * Hc;

    cudaFuncSetAttribute(fused_mma_kernel,
                         cudaFuncAttributeMaxDynamicSharedMemorySize, DSMEM);

    prep_mem_kernel<<<(Mslots * Hc) / 256, 256>>>(mem);
    fused_mma_kernel<<<NCTA, THREADS, DSMEM>>>(x, mem, comb, readm);
    mean_reduce2_kernel<<<(Bc * Hc) / 256, 256>>>();
    wc_kernel<<<(Bc * Hc * 32) / 256, 256>>>(W, bw);
    newmem_kernel<<<(Bc * Mslots * Hc / 4) / 256, 256>>>(mem, newm);
}

// round 14
// speedup vs baseline: 1.0790x; 1.0790x over previous
#include <cuda_runtime.h>
#include <cuda_fp16.h>
#include <cstdint>

// ---------------- problem constants ----------------
#define Hc      2048
#define Mslots  256
#define Bc      8
#define Sc      4096
#define NROWS   (Bc * Sc)        // 32768
#define BRr     64               // rows per CTA
#define THREADS 256              // 8 warps; 2 CTAs/SM
#define NCTA    (NROWS / BRr)    // 512

// ---------------- dynamic smem layout (74KB) ----------------
// phase 1 (single-buffered k-chunks of 64, fp16 single) — identical to round 12:
#define XA_F16 0                 // x fp16   [64 x 64k]   8KB
#define MB_F16 8192              // mem fp16 [256 x 64k] 32KB  (end 40KB)
// logits scratch (after phase 1; aliases staging):
#define LG_OFF 0                 // fp32 [64 rows][256]  64KB
#define LG_STR 256
// mean-pool scratch (non-aliased):
#define MSUM   65536             // fp32 [2048] per-CTA column sums (8KB)
#define MSW    73728             // fp32 [8][64] per-warp partials (2KB)
#define DSMEM  75776

#define SWZ128(o) ((o) ^ (((o) >> 3) & 0x70))

// ---------------- scratch (__device__ globals) ----------------
__device__ __align__(16) __half g_memF[Mslots * Hc];     // mem fp16 [slot][k]
__device__ __align__(16) float  g_part2[NCTA * Hc];      // per-CTA column sums (4MB)
__device__ __align__(16) float  g_xmean[Bc * Hc];
__device__ __align__(16) float  g_wc[Bc * Hc];

// ---------------- helpers ----------------
__device__ __forceinline__ uint32_t smem_u32(const void* p) {
    uint32_t a;
    asm("{ .reg .u64 t; cvta.to.shared.u64 t, %1; cvt.u32.u64 %0, t; }" : "=r"(a) : "l"(p));
    return a;
}
__device__ __forceinline__ void ldsm_x4(uint32_t (&r)[4], uint32_t addr) {
    asm volatile("ldmatrix.sync.aligned.m8n8.x4.shared.b16 {%0,%1,%2,%3}, [%4];"
                 : "=r"(r[0]), "=r"(r[1]), "=r"(r[2]), "=r"(r[3]) : "r"(addr));
}
__device__ __forceinline__ void mma_f16(float (&c)[4], const uint32_t (&a)[4],
                                        uint32_t b0, uint32_t b1) {
    asm volatile(
        "mma.sync.aligned.m16n8k16.row.col.f32.f16.f16.f32 "
        "{%0,%1,%2,%3}, {%4,%5,%6,%7}, {%8,%9}, {%0,%1,%2,%3};"
        : "+f"(c[0]), "+f"(c[1]), "+f"(c[2]), "+f"(c[3])
        : "r"(a[0]), "r"(a[1]), "r"(a[2]), "r"(a[3]), "r"(b0), "r"(b1));
}

// ======================= prep: mem -> fp16 =======================
__global__ void prep_mem_kernel(const float* __restrict__ mem) {
    int i = blockIdx.x * 256 + threadIdx.x;
    g_memF[i] = __float2half_rn(mem[i]);
}

// ======================= fused kernel =======================
extern __shared__ __align__(1024) char dsm[];

__global__ __launch_bounds__(THREADS, 2)
void fused_mma_kernel(const float* __restrict__ x,
                      const float* __restrict__ memf,
                      float* __restrict__ comb,
                      float* __restrict__ readm) {
    const int tid = threadIdx.x;
    const int lane = tid & 31;
    const int wid = tid >> 5;
    const int wm = wid >> 2;             // 0..1 (M position)
    const int wn = wid & 3;              // 0..3 (N position)
    const int row0 = blockIdx.x * BRr;
    const uint32_t sb = smem_u32(dsm);
    const int b_nfp = (lane >> 4) & 1;
    const int b_kh  = (lane >> 3) & 1;
    const int b_row = lane & 7;

    float* msum = (float*)(dsm + MSUM);
    float* msw  = (float*)(dsm + MSW);

    // ---------------- phase 1: coarse scores = x @ mem^T (fp16, 1 product) ----------------
    float acc[2][8][4];
#pragma unroll
    for (int mf = 0; mf < 2; ++mf)
#pragma unroll
        for (int nf = 0; nf < 8; ++nf)
#pragma unroll
            for (int e = 0; e < 4; ++e) acc[mf][nf][e] = 0.f;

    for (int t = 0; t < 32; ++t) {
        const int k0 = t * 64;
        // stage x chunk (fp16) + free combined copy + mean partial
        float4 ps = make_float4(0.f, 0.f, 0.f, 0.f);
#pragma unroll
        for (int it = 0; it < 4; ++it) {
            int idx = it * 256 + tid;
            int r = idx >> 4, c4 = idx & 15;
            float4 v = *(const float4*)(x + (size_t)(row0 + r) * Hc + k0 + c4 * 4);
            *(float4*)(comb + (size_t)(row0 + r) * (2 * Hc) + k0 + c4 * 4) = v;
            ps.x += v.x; ps.y += v.y; ps.z += v.z; ps.w += v.w;
            __half2 h0 = __floats2half2_rn(v.x, v.y);
            __half2 h1 = __floats2half2_rn(v.z, v.w);
            uint32_t off = SWZ128((uint32_t)(r * 128 + c4 * 8));
            *(uint2*)(dsm + XA_F16 + off) =
                make_uint2(*reinterpret_cast<uint32_t*>(&h0), *reinterpret_cast<uint32_t*>(&h1));
        }
        // stage mem chunk (fp16)
#pragma unroll
        for (int it = 0; it < 8; ++it) {
            int idx = it * 256 + tid;
            int m = idx >> 3, c8 = idx & 7;
            uint32_t off = SWZ128((uint32_t)(m * 128 + c8 * 16));
            *(uint4*)(dsm + MB_F16 + off) = *(const uint4*)(g_memF + (size_t)m * Hc + k0 + c8 * 8);
        }
        // fold row-pairs (lanes l and l^16 share the same column group tid&15)
        ps.x += __shfl_xor_sync(0xffffffffu, ps.x, 16);
        ps.y += __shfl_xor_sync(0xffffffffu, ps.y, 16);
        ps.z += __shfl_xor_sync(0xffffffffu, ps.z, 16);
        ps.w += __shfl_xor_sync(0xffffffffu, ps.w, 16);
        if (lane < 16)
            *(float4*)(msw + wid * 64 + lane * 4) = ps;
        __syncthreads();
        // fold 8 warps' partials into per-CTA column sums for this chunk
        if (tid < 64) {
            float s = 0.f;
#pragma unroll
            for (int w = 0; w < 8; ++w) s += msw[w * 64 + tid];
            msum[t * 64 + tid] = s;
        }
        // compute chunk
#pragma unroll
        for (int ks = 0; ks < 4; ++ks) {
            const uint32_t kb = (uint32_t)ks * 32;
            uint32_t af[2][4];
#pragma unroll
            for (int mf = 0; mf < 2; ++mf) {
                int row = wm * 32 + mf * 16 + (lane & 15);
                uint32_t ao = SWZ128((uint32_t)(row * 128) + kb + ((uint32_t)(lane >> 4) << 4));
                ldsm_x4(af[mf], sb + XA_F16 + ao);
            }
#pragma unroll
            for (int nf2 = 0; nf2 < 4; ++nf2) {
                int slot = wn * 64 + nf2 * 16 + b_nfp * 8 + b_row;
                uint32_t bofs = SWZ128((uint32_t)(slot * 128) + kb + ((uint32_t)b_kh << 4));
                uint32_t b4[4];
                ldsm_x4(b4, sb + MB_F16 + bofs);
#pragma unroll
                for (int h = 0; h < 2; ++h) {
                    const int nf = nf2 * 2 + h;
#pragma unroll
                    for (int mf = 0; mf < 2; ++mf)
                        mma_f16(acc[mf][nf], af[mf], b4[2 * h], b4[2 * h + 1]);
                }
            }
        }
        __syncthreads();
    }

    // ---------------- flush per-CTA column sums ----------------
    for (int i = tid; i < Hc; i += THREADS)
        g_part2[(size_t)blockIdx.x * Hc + i] = msum[i];

    // ---------------- dump coarse logits (fp32) to smem ----------------
    float* lg = (float*)(dsm + LG_OFF);
#pragma unroll
    for (int mf = 0; mf < 2; ++mf)
#pragma unroll
        for (int rh = 0; rh < 2; ++rh) {
            int rloc = wm * 32 + mf * 16 + (lane >> 2) + rh * 8;
#pragma unroll
            for (int nf = 0; nf < 8; ++nf) {
                int col = wn * 64 + nf * 8 + (lane & 3) * 2;
                *(float2*)(lg + rloc * LG_STR + col) =
                    make_float2(acc[mf][nf][rh * 2], acc[mf][nf][rh * 2 + 1]);
            }
        }
    __syncthreads();

    // ---------------- per-row: refine -> softmax -> sparse-exact output ----------------
    for (int rr = 0; rr < 8; ++rr) {
        const int rl = wid * 8 + rr;
        float* Lrow = lg + rl * LG_STR;

        // coarse max
        float cm = -3.4e38f;
#pragma unroll
        for (int i = 0; i < 8; ++i) cm = fmaxf(cm, Lrow[lane + i * 32]);
#pragma unroll
        for (int d = 16; d >= 1; d >>= 1)
            cm = fmaxf(cm, __shfl_xor_sync(0xffffffffu, cm, d));
        const float thr = cm - 14.0f;

        // exact recompute of candidate slots (fp32 from global)
#pragma unroll
        for (int i = 0; i < 8; ++i) {
            int slot = lane + i * 32;
            bool cand = Lrow[slot] > thr;
            unsigned mask = __ballot_sync(0xffffffffu, cand);
            while (mask) {
                int src = __ffs(mask) - 1;
                mask &= mask - 1;
                int s2 = src + i * 32;
                const float4* xp = (const float4*)(x + (size_t)(row0 + rl) * Hc);
                const float4* mp = (const float4*)(memf + (size_t)s2 * Hc);
                float d = 0.f;
                for (int k = lane; k < Hc / 4; k += 32) {
                    float4 a = xp[k], b = mp[k];
                    d += a.x * b.x + a.y * b.y + a.z * b.z + a.w * b.w;
                }
#pragma unroll
                for (int dd = 16; dd >= 1; dd >>= 1)
                    d += __shfl_xor_sync(0xffffffffu, d, dd);
                if (lane == 0) Lrow[s2] = d;
            }
        }
        __syncwarp();

        // exact max + sum over all 256 (refined where it matters)
        float m2 = -3.4e38f;
#pragma unroll
        for (int i = 0; i < 8; ++i) m2 = fmaxf(m2, Lrow[lane + i * 32]);
#pragma unroll
        for (int d = 16; d >= 1; d >>= 1)
            m2 = fmaxf(m2, __shfl_xor_sync(0xffffffffu, m2, d));
        float s = 0.f;
#pragma unroll
        for (int i = 0; i < 8; ++i) s += __expf(Lrow[lane + i * 32] - m2);
#pragma unroll
        for (int d = 16; d >= 1; d >>= 1)
            s += __shfl_xor_sync(0xffffffffu, s, d);
        const float inv = 1.0f / s;
        const float thr2 = m2 - 14.0f;

        // output: read[rl][:] = sum_{cand} w_c * mem[c][:]  (fp32 exact, 4 h-chunks)
        float* rp = readm + (size_t)(row0 + rl) * Hc;
        float* cp = comb + (size_t)(row0 + rl) * (2 * Hc) + Hc;
#pragma unroll
        for (int hc = 0; hc < 4; ++hc) {
            float4 out[4];
#pragma unroll
            for (int j = 0; j < 4; ++j) out[j] = make_float4(0.f, 0.f, 0.f, 0.f);
#pragma unroll
            for (int i = 0; i < 8; ++i) {
                bool cand = Lrow[lane + i * 32] > thr2;
                unsigned mask = __ballot_sync(0xffffffffu, cand);
                while (mask) {
                    int src = __ffs(mask) - 1;
                    mask &= mask - 1;
                    int s2 = src + i * 32;
                    float w = __expf(Lrow[s2] - m2) * inv;
                    const float4* mp = (const float4*)(memf + (size_t)s2 * Hc) + hc * 128;
#pragma unroll
                    for (int j = 0; j < 4; ++j) {
                        float4 mv = mp[lane + j * 32];
                        out[j].x += w * mv.x;
                        out[j].y += w * mv.y;
                        out[j].z += w * mv.z;
                        out[j].w += w * mv.w;
                    }
                }
            }
#pragma unroll
            for (int j = 0; j < 4; ++j) {
                int h4 = hc * 128 + lane + j * 32;
                *(float4*)(rp + h4 * 4) = out[j];
                *(float4*)(cp + h4 * 4) = out[j];
            }
        }
    }
}

// ======================= write path =======================
__global__ void mean_reduce2_kernel() {
    const int i = blockIdx.x * 256 + threadIdx.x;   // 0 .. Bc*Hc-1
    const int b = i >> 11, col = i & (Hc - 1);
    float s = 0.f;
    const int c0 = b * (NCTA / Bc);                 // 64 CTAs per batch
    for (int j = 0; j < NCTA / Bc; ++j)
        s += g_part2[(size_t)(c0 + j) * Hc + col];
    g_xmean[i] = s * (1.0f / (float)Sc);
}

__global__ void wc_kernel(const float* __restrict__ W, const float* __restrict__ bw) {
    const int gw = (blockIdx.x * blockDim.x + threadIdx.x) >> 5;
    const int lane = threadIdx.x & 31;
    if (gw >= Bc * Hc) return;
    const int b = gw >> 11, i = gw & (Hc - 1);
    const float4* wr = (const float4*)(W + (size_t)i * Hc);
    const float4* xm = (const float4*)(g_xmean + (size_t)b * Hc);
    float s = 0.f;
    for (int k = lane; k < Hc / 4; k += 32) {
        float4 w4 = wr[k], x4 = xm[k];
        s += w4.x * x4.x + w4.y * x4.y + w4.z * x4.z + w4.w * x4.w;
    }
#pragma unroll
    for (int d = 16; d >= 1; d >>= 1) s += __shfl_xor_sync(0xffffffffu, s, d);
    if (lane == 0) g_wc[gw] = s + bw[i];
}

__global__ void newmem_kernel(const float* __restrict__ mem, float* __restrict__ outnm) {
    const size_t idx = (size_t)blockIdx.x * 256 + threadIdx.x;
    const int h4 = (int)(idx & (Hc / 4 - 1));
    const size_t rest = idx >> 9;
    const int m = (int)(rest & (Mslots - 1));
    const int b = (int)(rest >> 8);
    float4 mv = *(const float4*)(mem + (size_t)m * Hc + h4 * 4);
    float4 wv = *(const float4*)(g_wc + (size_t)b * Hc + h4 * 4);
    ((float4*)outnm)[idx] = make_float4(0.9f * mv.x + 0.1f * wv.x, 0.9f * mv.y + 0.1f * wv.y,
                                        0.9f * mv.z + 0.1f * wv.z, 0.9f * mv.w + 0.1f * wv.w);
}

// ======================= launch =======================
extern "C" void kernel_launch(void* const* d_in, const int* in_sizes, int n_in,
                              void* d_out, int out_size) {
    const float* x   = (const float*)d_in[0];
    const float* mem = (const float*)d_in[1];
    const float* W   = (const float*)d_in[2];
    const float* bw  = (const float*)d_in[3];

    float* comb  = (float*)d_out;
    float* readm = comb + (size_t)NROWS * 2 * Hc;
    float* newm  = readm + (size_t)NROWS * Hc;

    cudaFuncSetAttribute(fused_mma_kernel,
                         cudaFuncAttributeMaxDynamicSharedMemorySize, DSMEM);

    prep_mem_kernel<<<(Mslots * Hc) / 256, 256>>>(mem);
    fused_mma_kernel<<<NCTA, THREADS, DSMEM>>>(x, mem, comb, readm);
    mean_reduce2_kernel<<<(Bc * Hc) / 256, 256>>>();
    wc_kernel<<<(Bc * Hc * 32) / 256, 256>>>(W, bw);
    newmem_kernel<<<(Bc * Mslots * Hc / 4) / 256, 256>>>(mem, newm);
}

// round 15
// speedup vs baseline: 1.3008x; 1.2056x over previous
#include <cuda_runtime.h>
#include <cuda_fp16.h>
#include <cstdint>

// ---------------- problem constants ----------------
#define Hc      2048
#define Mslots  256
#define Bc      8
#define Sc      4096
#define NROWS   (Bc * Sc)        // 32768
#define BRr     64               // rows per CTA
#define THREADS 256              // 8 warps; 2 CTAs/SM

// ---------------- dynamic smem layout (64KB) ----------------
// phase 1 (single-buffered k-chunks of 64, fp16 single):
#define XA_F16 0                 // x fp16   [64 x 64k]   8KB
#define MB_F16 8192              // mem fp16 [256 x 64k] 32KB  (end 40KB)
// logits scratch (after phase 1; reuses allocation):
#define LG_OFF 0                 // fp32 [64 rows][256]  64KB
#define LG_STR 256
#define DSMEM  65536

#define SWZ128(o) ((o) ^ (((o) >> 3) & 0x70))

// ---------------- scratch (__device__ globals) ----------------
__device__ __align__(16) __half g_memF[Mslots * Hc];   // mem fp16 [slot][k]
#define SCHUNKS 32
__device__ __align__(16) float g_part[SCHUNKS * Bc * Hc];
__device__ __align__(16) float g_xmean[Bc * Hc];
__device__ __align__(16) float g_wc[Bc * Hc];

// ---------------- helpers ----------------
__device__ __forceinline__ uint32_t smem_u32(const void* p) {
    uint32_t a;
    asm("{ .reg .u64 t; cvta.to.shared.u64 t, %1; cvt.u32.u64 %0, t; }" : "=r"(a) : "l"(p));
    return a;
}
__device__ __forceinline__ void ldsm_x4(uint32_t (&r)[4], uint32_t addr) {
    asm volatile("ldmatrix.sync.aligned.m8n8.x4.shared.b16 {%0,%1,%2,%3}, [%4];"
                 : "=r"(r[0]), "=r"(r[1]), "=r"(r[2]), "=r"(r[3]) : "r"(addr));
}
__device__ __forceinline__ void mma_f16(float (&c)[4], const uint32_t (&a)[4],
                                        uint32_t b0, uint32_t b1) {
    asm volatile(
        "mma.sync.aligned.m16n8k16.row.col.f32.f16.f16.f32 "
        "{%0,%1,%2,%3}, {%4,%5,%6,%7}, {%8,%9}, {%0,%1,%2,%3};"
        : "+f"(c[0]), "+f"(c[1]), "+f"(c[2]), "+f"(c[3])
        : "r"(a[0]), "r"(a[1]), "r"(a[2]), "r"(a[3]), "r"(b0), "r"(b1));
}
__device__ __forceinline__ void cp_async16(uint32_t dst, const void* src) {
    asm volatile("cp.async.cg.shared.global [%0], [%1], 16;" :: "r"(dst), "l"(src));
}
#define CP_COMMIT() asm volatile("cp.async.commit_group;" ::: "memory")
#define CP_WAIT0()  asm volatile("cp.async.wait_group 0;" ::: "memory")

// ======================= prep: mem -> fp16 =======================
__global__ void prep_mem_kernel(const float* __restrict__ mem) {
    int i = blockIdx.x * 256 + threadIdx.x;
    g_memF[i] = __float2half_rn(mem[i]);
}

// ======================= fused kernel =======================
extern __shared__ __align__(1024) char dsm[];

__global__ __launch_bounds__(THREADS, 2)
void fused_mma_kernel(const float* __restrict__ x,
                      const float* __restrict__ memf,
                      float* __restrict__ comb,
                      float* __restrict__ readm) {
    const int tid = threadIdx.x;
    const int lane = tid & 31;
    const int wid = tid >> 5;
    const int wm = wid >> 2;             // 0..1 (M position)
    const int wn = wid & 3;              // 0..3 (N position)
    const int row0 = blockIdx.x * BRr;
    const uint32_t sb = smem_u32(dsm);
    const int b_nfp = (lane >> 4) & 1;
    const int b_kh  = (lane >> 3) & 1;
    const int b_row = lane & 7;

    // ---------------- phase 1: coarse scores = x @ mem^T (fp16, 1 product) ----------------
    float acc[2][8][4];
#pragma unroll
    for (int mf = 0; mf < 2; ++mf)
#pragma unroll
        for (int nf = 0; nf < 8; ++nf)
#pragma unroll
            for (int e = 0; e < 4; ++e) acc[mf][nf][e] = 0.f;

    for (int t = 0; t < 32; ++t) {
        const int k0 = t * 64;
        // stage mem chunk via cp.async first (in flight during x staging)
#pragma unroll
        for (int it = 0; it < 8; ++it) {
            int idx = it * 256 + tid;
            int m = idx >> 3, c8 = idx & 7;
            uint32_t off = SWZ128((uint32_t)(m * 128 + c8 * 16));
            cp_async16(sb + MB_F16 + off, g_memF + (size_t)m * Hc + k0 + c8 * 8);
        }
        CP_COMMIT();
        // stage x chunk (front-batched loads -> comb copy + fp16 convert)
        float4 v[4];
#pragma unroll
        for (int it = 0; it < 4; ++it) {
            int idx = it * 256 + tid;
            int r = idx >> 4, c4 = idx & 15;
            v[it] = *(const float4*)(x + (size_t)(row0 + r) * Hc + k0 + c4 * 4);
        }
#pragma unroll
        for (int it = 0; it < 4; ++it) {
            int idx = it * 256 + tid;
            int r = idx >> 4, c4 = idx & 15;
            *(float4*)(comb + (size_t)(row0 + r) * (2 * Hc) + k0 + c4 * 4) = v[it];
            __half2 h0 = __floats2half2_rn(v[it].x, v[it].y);
            __half2 h1 = __floats2half2_rn(v[it].z, v[it].w);
            uint32_t off = SWZ128((uint32_t)(r * 128 + c4 * 8));
            *(uint2*)(dsm + XA_F16 + off) =
                make_uint2(*reinterpret_cast<uint32_t*>(&h0), *reinterpret_cast<uint32_t*>(&h1));
        }
        CP_WAIT0();
        __syncthreads();
        // compute chunk
#pragma unroll
        for (int ks = 0; ks < 4; ++ks) {
            const uint32_t kb = (uint32_t)ks * 32;
            uint32_t af[2][4];
#pragma unroll
            for (int mf = 0; mf < 2; ++mf) {
                int row = wm * 32 + mf * 16 + (lane & 15);
                uint32_t ao = SWZ128((uint32_t)(row * 128) + kb + ((uint32_t)(lane >> 4) << 4));
                ldsm_x4(af[mf], sb + XA_F16 + ao);
            }
#pragma unroll
            for (int nf2 = 0; nf2 < 4; ++nf2) {
                int slot = wn * 64 + nf2 * 16 + b_nfp * 8 + b_row;
                uint32_t bofs = SWZ128((uint32_t)(slot * 128) + kb + ((uint32_t)b_kh << 4));
                uint32_t b4[4];
                ldsm_x4(b4, sb + MB_F16 + bofs);
#pragma unroll
                for (int h = 0; h < 2; ++h) {
                    const int nf = nf2 * 2 + h;
#pragma unroll
                    for (int mf = 0; mf < 2; ++mf)
                        mma_f16(acc[mf][nf], af[mf], b4[2 * h], b4[2 * h + 1]);
                }
            }
        }
        __syncthreads();
    }

    // ---------------- dump coarse logits (fp32) to smem ----------------
    float* lg = (float*)(dsm + LG_OFF);
#pragma unroll
    for (int mf = 0; mf < 2; ++mf)
#pragma unroll
        for (int rh = 0; rh < 2; ++rh) {
            int rloc = wm * 32 + mf * 16 + (lane >> 2) + rh * 8;
#pragma unroll
            for (int nf = 0; nf < 8; ++nf) {
                int col = wn * 64 + nf * 8 + (lane & 3) * 2;
                *(float2*)(lg + rloc * LG_STR + col) =
                    make_float2(acc[mf][nf][rh * 2], acc[mf][nf][rh * 2 + 1]);
            }
        }
    __syncthreads();

    // ---------------- per-row: refine -> softmax -> sparse-exact output ----------------
    for (int rr = 0; rr < 8; ++rr) {
        const int rl = wid * 8 + rr;
        float* Lrow = lg + rl * LG_STR;

        // coarse max
        float cm = -3.4e38f;
#pragma unroll
        for (int i = 0; i < 8; ++i) cm = fmaxf(cm, Lrow[lane + i * 32]);
#pragma unroll
        for (int d = 16; d >= 1; d >>= 1)
            cm = fmaxf(cm, __shfl_xor_sync(0xffffffffu, cm, d));
        const float thr = cm - 14.0f;

        // exact recompute of candidate slots (fp32 from global)
#pragma unroll
        for (int i = 0; i < 8; ++i) {
            int slot = lane + i * 32;
            bool cand = Lrow[slot] > thr;
            unsigned mask = __ballot_sync(0xffffffffu, cand);
            while (mask) {
                int src = __ffs(mask) - 1;
                mask &= mask - 1;
                int s2 = src + i * 32;
                const float4* xp = (const float4*)(x + (size_t)(row0 + rl) * Hc);
                const float4* mp = (const float4*)(memf + (size_t)s2 * Hc);
                float d = 0.f;
                for (int k = lane; k < Hc / 4; k += 32) {
                    float4 a = xp[k], b = mp[k];
                    d += a.x * b.x + a.y * b.y + a.z * b.z + a.w * b.w;
                }
#pragma unroll
                for (int dd = 16; dd >= 1; dd >>= 1)
                    d += __shfl_xor_sync(0xffffffffu, d, dd);
                if (lane == 0) Lrow[s2] = d;
            }
        }
        __syncwarp();

        // exact max + sum over all 256 (refined where it matters)
        float m2 = -3.4e38f;
#pragma unroll
        for (int i = 0; i < 8; ++i) m2 = fmaxf(m2, Lrow[lane + i * 32]);
#pragma unroll
        for (int d = 16; d >= 1; d >>= 1)
            m2 = fmaxf(m2, __shfl_xor_sync(0xffffffffu, m2, d));
        float s = 0.f;
#pragma unroll
        for (int i = 0; i < 8; ++i) s += __expf(Lrow[lane + i * 32] - m2);
#pragma unroll
        for (int d = 16; d >= 1; d >>= 1)
            s += __shfl_xor_sync(0xffffffffu, s, d);
        const float inv = 1.0f / s;
        const float thr2 = m2 - 14.0f;

        // output: read[rl][:] = sum_{cand} w_c * mem[c][:]  (fp32 exact, 4 h-chunks)
        float* rp = readm + (size_t)(row0 + rl) * Hc;
        float* cp = comb + (size_t)(row0 + rl) * (2 * Hc) + Hc;
#pragma unroll
        for (int hc = 0; hc < 4; ++hc) {
            float4 out[4];
#pragma unroll
            for (int j = 0; j < 4; ++j) out[j] = make_float4(0.f, 0.f, 0.f, 0.f);
#pragma unroll
            for (int i = 0; i < 8; ++i) {
                bool cand = Lrow[lane + i * 32] > thr2;
                unsigned mask = __ballot_sync(0xffffffffu, cand);
                while (mask) {
                    int src = __ffs(mask) - 1;
                    mask &= mask - 1;
                    int s2 = src + i * 32;
                    float w = __expf(Lrow[s2] - m2) * inv;
                    const float4* mp = (const float4*)(memf + (size_t)s2 * Hc) + hc * 128;
#pragma unroll
                    for (int j = 0; j < 4; ++j) {
                        float4 mv = mp[lane + j * 32];
                        out[j].x += w * mv.x;
                        out[j].y += w * mv.y;
                        out[j].z += w * mv.z;
                        out[j].w += w * mv.w;
                    }
                }
            }
#pragma unroll
            for (int j = 0; j < 4; ++j) {
                int h4 = hc * 128 + lane + j * 32;
                *(float4*)(rp + h4 * 4) = out[j];
                *(float4*)(cp + h4 * 4) = out[j];
            }
        }
    }
}

// ======================= write path =======================
__global__ void mean_part_kernel(const float* __restrict__ x) {
    const int sc = blockIdx.x, b = blockIdx.y, tid = threadIdx.x;
    const int SS = Sc / SCHUNKS;
    float acc[8] = {0, 0, 0, 0, 0, 0, 0, 0};
    const float* xp = x + ((size_t)b * Sc + (size_t)sc * SS) * Hc;
    for (int s = 0; s < SS; ++s) {
#pragma unroll
        for (int hh = 0; hh < 8; ++hh)
            acc[hh] += xp[(size_t)s * Hc + tid + hh * 256];
    }
#pragma unroll
    for (int hh = 0; hh < 8; ++hh)
        g_part[((size_t)sc * Bc + b) * Hc + tid + hh * 256] = acc[hh];
}

__global__ void mean_reduce_kernel() {
    const int i = blockIdx.x * 256 + threadIdx.x;
    float s = 0.f;
#pragma unroll
    for (int sc = 0; sc < SCHUNKS; ++sc) s += g_part[(size_t)sc * Bc * Hc + i];
    g_xmean[i] = s * (1.0f / (float)Sc);
}

__global__ void wc_kernel(const float* __restrict__ W, const float* __restrict__ bw) {
    const int gw = (blockIdx.x * blockDim.x + threadIdx.x) >> 5;
    const int lane = threadIdx.x & 31;
    if (gw >= Bc * Hc) return;
    const int b = gw >> 11, i = gw & (Hc - 1);
    const float4* wr = (const float4*)(W + (size_t)i * Hc);
    const float4* xm = (const float4*)(g_xmean + (size_t)b * Hc);
    float s = 0.f;
    for (int k = lane; k < Hc / 4; k += 32) {
        float4 w4 = wr[k], x4 = xm[k];
        s += w4.x * x4.x + w4.y * x4.y + w4.z * x4.z + w4.w * x4.w;
    }
#pragma unroll
    for (int d = 16; d >= 1; d >>= 1) s += __shfl_xor_sync(0xffffffffu, s, d);
    if (lane == 0) g_wc[gw] = s + bw[i];
}

__global__ void newmem_kernel(const float* __restrict__ mem, float* __restrict__ outnm) {
    const size_t idx = (size_t)blockIdx.x * 256 + threadIdx.x;
    const int h4 = (int)(idx & (Hc / 4 - 1));
    const size_t rest = idx >> 9;
    const int m = (int)(rest & (Mslots - 1));
    const int b = (int)(rest >> 8);
    float4 mv = *(const float4*)(mem + (size_t)m * Hc + h4 * 4);
    float4 wv = *(const float4*)(g_wc + (size_t)b * Hc + h4 * 4);
    ((float4*)outnm)[idx] = make_float4(0.9f * mv.x + 0.1f * wv.x, 0.9f * mv.y + 0.1f * wv.y,
                                        0.9f * mv.z + 0.1f * wv.z, 0.9f * mv.w + 0.1f * wv.w);
}

// ======================= launch =======================
extern "C" void kernel_launch(void* const* d_in, const int* in_sizes, int n_in,
                              void* d_out, int out_size) {
    const float* x   = (const float*)d_in[0];
    const float* mem = (const float*)d_in[1];
    const float* W   = (const float*)d_in[2];
    const float* bw  = (const float*)d_in[3];

    float* comb  = (float*)d_out;
    float* readm = comb + (size_t)NROWS * 2 * Hc;
    float* newm  = readm + (size_t)NROWS * Hc;

    cudaFuncSetAttribute(fused_mma_kernel,
                         cudaFuncAttributeMaxDynamicSharedMemorySize, DSMEM);

    prep_mem_kernel<<<(Mslots * Hc) / 256, 256>>>(mem);
    mean_part_kernel<<<dim3(SCHUNKS, Bc), 256>>>(x);
    mean_reduce_kernel<<<(Bc * Hc) / 256, 256>>>();
    wc_kernel<<<(Bc * Hc * 32) / 256, 256>>>(W, bw);
    newmem_kernel<<<(Bc * Mslots * Hc / 4) / 256, 256>>>(mem, newm);
    fused_mma_kernel<<<NROWS / BRr, THREADS, DSMEM>>>(x, mem, comb, readm);
}

// round 16
// speedup vs baseline: 1.3753x; 1.0573x over previous
#include <cuda_runtime.h>
#include <cuda_fp16.h>
#include <cstdint>

// ---------------- problem constants ----------------
#define Hc      2048
#define Mslots  256
#define Bc      8
#define Sc      4096
#define NROWS   (Bc * Sc)        // 32768
#define BRr     64               // rows per CTA
#define THREADS 256              // 8 warps; 2 CTAs/SM

// ---------------- dynamic smem layout (64KB) ----------------
#define XA_F16 0                 // x fp16   [64 x 64k]   8KB
#define MB_F16 8192              // mem fp16 [256 x 64k] 32KB  (end 40KB)
#define LG_OFF 0                 // fp32 [64 rows][256]  64KB (aliases staging)
#define LG_STR 256
#define DSMEM  65536

#define SWZ128(o) ((o) ^ (((o) >> 3) & 0x70))

// ---------------- scratch (__device__ globals) ----------------
__device__ __align__(16) __half g_memF[Mslots * Hc];   // mem fp16 [slot][k]
#define SCHUNKS 32
__device__ __align__(16) float g_part[SCHUNKS * Bc * Hc];
__device__ __align__(16) float g_xmean[Bc * Hc];
__device__ __align__(16) float g_wc[Bc * Hc];

// ---------------- helpers ----------------
__device__ __forceinline__ uint32_t smem_u32(const void* p) {
    uint32_t a;
    asm("{ .reg .u64 t; cvta.to.shared.u64 t, %1; cvt.u32.u64 %0, t; }" : "=r"(a) : "l"(p));
    return a;
}
__device__ __forceinline__ void ldsm_x4(uint32_t (&r)[4], uint32_t addr) {
    asm volatile("ldmatrix.sync.aligned.m8n8.x4.shared.b16 {%0,%1,%2,%3}, [%4];"
                 : "=r"(r[0]), "=r"(r[1]), "=r"(r[2]), "=r"(r[3]) : "r"(addr));
}
__device__ __forceinline__ void mma_f16(float (&c)[4], const uint32_t (&a)[4],
                                        uint32_t b0, uint32_t b1) {
    asm volatile(
        "mma.sync.aligned.m16n8k16.row.col.f32.f16.f16.f32 "
        "{%0,%1,%2,%3}, {%4,%5,%6,%7}, {%8,%9}, {%0,%1,%2,%3};"
        : "+f"(c[0]), "+f"(c[1]), "+f"(c[2]), "+f"(c[3])
        : "r"(a[0]), "r"(a[1]), "r"(a[2]), "r"(a[3]), "r"(b0), "r"(b1));
}
__device__ __forceinline__ void cp_async16(uint32_t dst, const void* src) {
    asm volatile("cp.async.cg.shared.global [%0], [%1], 16;" :: "r"(dst), "l"(src));
}
#define CP_COMMIT() asm volatile("cp.async.commit_group;" ::: "memory")
#define CP_WAIT0()  asm volatile("cp.async.wait_group 0;" ::: "memory")

// ======================= prep: mem -> fp16 =======================
__global__ void prep_mem_kernel(const float* __restrict__ mem) {
    int i = blockIdx.x * 256 + threadIdx.x;
    g_memF[i] = __float2half_rn(mem[i]);
}

// ======================= fused kernel =======================
extern __shared__ __align__(1024) char dsm[];

__global__ __launch_bounds__(THREADS, 2)
void fused_mma_kernel(const float* __restrict__ x,
                      const float* __restrict__ memf,
                      float* __restrict__ comb,
                      float* __restrict__ readm) {
    const int tid = threadIdx.x;
    const int lane = tid & 31;
    const int wid = tid >> 5;
    const int wm = wid >> 2;             // 0..1 (M position)
    const int wn = wid & 3;              // 0..3 (N position)
    const int row0 = blockIdx.x * BRr;
    const uint32_t sb = smem_u32(dsm);
    const int b_nfp = (lane >> 4) & 1;
    const int b_kh  = (lane >> 3) & 1;
    const int b_row = lane & 7;

    // ---------------- phase 1: coarse scores = x @ mem^T (fp16, 1 product) ----------------
    float acc[2][8][4];
#pragma unroll
    for (int mf = 0; mf < 2; ++mf)
#pragma unroll
        for (int nf = 0; nf < 8; ++nf)
#pragma unroll
            for (int e = 0; e < 4; ++e) acc[mf][nf][e] = 0.f;

    for (int t = 0; t < 32; ++t) {
        const int k0 = t * 64;
        // stage mem chunk via cp.async first (in flight during x staging)
#pragma unroll
        for (int it = 0; it < 8; ++it) {
            int idx = it * 256 + tid;
            int m = idx >> 3, c8 = idx & 7;
            uint32_t off = SWZ128((uint32_t)(m * 128 + c8 * 16));
            cp_async16(sb + MB_F16 + off, g_memF + (size_t)m * Hc + k0 + c8 * 8);
        }
        CP_COMMIT();
        // stage x chunk (front-batched loads -> comb copy + fp16 convert)
        float4 v[4];
#pragma unroll
        for (int it = 0; it < 4; ++it) {
            int idx = it * 256 + tid;
            int r = idx >> 4, c4 = idx & 15;
            v[it] = *(const float4*)(x + (size_t)(row0 + r) * Hc + k0 + c4 * 4);
        }
#pragma unroll
        for (int it = 0; it < 4; ++it) {
            int idx = it * 256 + tid;
            int r = idx >> 4, c4 = idx & 15;
            *(float4*)(comb + (size_t)(row0 + r) * (2 * Hc) + k0 + c4 * 4) = v[it];
            __half2 h0 = __floats2half2_rn(v[it].x, v[it].y);
            __half2 h1 = __floats2half2_rn(v[it].z, v[it].w);
            uint32_t off = SWZ128((uint32_t)(r * 128 + c4 * 8));
            *(uint2*)(dsm + XA_F16 + off) =
                make_uint2(*reinterpret_cast<uint32_t*>(&h0), *reinterpret_cast<uint32_t*>(&h1));
        }
        CP_WAIT0();
        __syncthreads();
        // compute chunk
#pragma unroll
        for (int ks = 0; ks < 4; ++ks) {
            const uint32_t kb = (uint32_t)ks * 32;
            uint32_t af[2][4];
#pragma unroll
            for (int mf = 0; mf < 2; ++mf) {
                int row = wm * 32 + mf * 16 + (lane & 15);
                uint32_t ao = SWZ128((uint32_t)(row * 128) + kb + ((uint32_t)(lane >> 4) << 4));
                ldsm_x4(af[mf], sb + XA_F16 + ao);
            }
#pragma unroll
            for (int nf2 = 0; nf2 < 4; ++nf2) {
                int slot = wn * 64 + nf2 * 16 + b_nfp * 8 + b_row;
                uint32_t bofs = SWZ128((uint32_t)(slot * 128) + kb + ((uint32_t)b_kh << 4));
                uint32_t b4[4];
                ldsm_x4(b4, sb + MB_F16 + bofs);
#pragma unroll
                for (int h = 0; h < 2; ++h) {
                    const int nf = nf2 * 2 + h;
#pragma unroll
                    for (int mf = 0; mf < 2; ++mf)
                        mma_f16(acc[mf][nf], af[mf], b4[2 * h], b4[2 * h + 1]);
                }
            }
        }
        __syncthreads();
    }

    // ---------------- dump coarse logits (fp32) to smem ----------------
    float* lg = (float*)(dsm + LG_OFF);
#pragma unroll
    for (int mf = 0; mf < 2; ++mf)
#pragma unroll
        for (int rh = 0; rh < 2; ++rh) {
            int rloc = wm * 32 + mf * 16 + (lane >> 2) + rh * 8;
#pragma unroll
            for (int nf = 0; nf < 8; ++nf) {
                int col = wn * 64 + nf * 8 + (lane & 3) * 2;
                *(float2*)(lg + rloc * LG_STR + col) =
                    make_float2(acc[mf][nf][rh * 2], acc[mf][nf][rh * 2 + 1]);
            }
        }
    __syncthreads();

    // ---------------- per-row: refine -> softmax -> sparse-exact output ----------------
    for (int rr = 0; rr < 8; ++rr) {
        const int rl = wid * 8 + rr;
        float* Lrow = lg + rl * LG_STR;

        // coarse max
        float cm = -3.4e38f;
#pragma unroll
        for (int i = 0; i < 8; ++i) cm = fmaxf(cm, Lrow[lane + i * 32]);
#pragma unroll
        for (int d = 16; d >= 1; d >>= 1)
            cm = fmaxf(cm, __shfl_xor_sync(0xffffffffu, cm, d));
        const float thr = cm - 14.0f;

        // exact recompute of candidate slots (fp32 from global)
#pragma unroll
        for (int i = 0; i < 8; ++i) {
            int slot = lane + i * 32;
            bool cand = Lrow[slot] > thr;
            unsigned mask = __ballot_sync(0xffffffffu, cand);
            while (mask) {
                int src = __ffs(mask) - 1;
                mask &= mask - 1;
                int s2 = src + i * 32;
                const float4* xp = (const float4*)(x + (size_t)(row0 + rl) * Hc);
                const float4* mp = (const float4*)(memf + (size_t)s2 * Hc);
                float d = 0.f;
                for (int k = lane; k < Hc / 4; k += 32) {
                    float4 a = xp[k], b = mp[k];
                    d += a.x * b.x + a.y * b.y + a.z * b.z + a.w * b.w;
                }
#pragma unroll
                for (int dd = 16; dd >= 1; dd >>= 1)
                    d += __shfl_xor_sync(0xffffffffu, d, dd);
                if (lane == 0) Lrow[s2] = d;
            }
        }
        __syncwarp();

        // exact max + sum over all 256 (refined where it matters)
        float m2 = -3.4e38f;
#pragma unroll
        for (int i = 0; i < 8; ++i) m2 = fmaxf(m2, Lrow[lane + i * 32]);
#pragma unroll
        for (int d = 16; d >= 1; d >>= 1)
            m2 = fmaxf(m2, __shfl_xor_sync(0xffffffffu, m2, d));
        float s = 0.f;
#pragma unroll
        for (int i = 0; i < 8; ++i) s += __expf(Lrow[lane + i * 32] - m2);
#pragma unroll
        for (int d = 16; d >= 1; d >>= 1)
            s += __shfl_xor_sync(0xffffffffu, s, d);
        const float inv = 1.0f / s;
        const float thr2 = m2 - 14.0f;

        // output: read[rl][:] = sum_{cand} w_c * mem[c][:]  (fp32 exact, 4 h-chunks)
        float* rp = readm + (size_t)(row0 + rl) * Hc;
        float* cp = comb + (size_t)(row0 + rl) * (2 * Hc) + Hc;
#pragma unroll
        for (int hc = 0; hc < 4; ++hc) {
            float4 out[4];
#pragma unroll
            for (int j = 0; j < 4; ++j) out[j] = make_float4(0.f, 0.f, 0.f, 0.f);
#pragma unroll
            for (int i = 0; i < 8; ++i) {
                bool cand = Lrow[lane + i * 32] > thr2;
                unsigned mask = __ballot_sync(0xffffffffu, cand);
                while (mask) {
                    int src = __ffs(mask) - 1;
                    mask &= mask - 1;
                    int s2 = src + i * 32;
                    float w = __expf(Lrow[s2] - m2) * inv;
                    const float4* mp = (const float4*)(memf + (size_t)s2 * Hc) + hc * 128;
#pragma unroll
                    for (int j = 0; j < 4; ++j) {
                        float4 mv = mp[lane + j * 32];
                        out[j].x += w * mv.x;
                        out[j].y += w * mv.y;
                        out[j].z += w * mv.z;
                        out[j].w += w * mv.w;
                    }
                }
            }
#pragma unroll
            for (int j = 0; j < 4; ++j) {
                int h4 = hc * 128 + lane + j * 32;
                *(float4*)(rp + h4 * 4) = out[j];
                *(float4*)(cp + h4 * 4) = out[j];
            }
        }
    }
}

// ======================= write path =======================
__global__ void mean_part_kernel(const float* __restrict__ x) {
    const int sc = blockIdx.x, b = blockIdx.y, tid = threadIdx.x;
    const int SS = Sc / SCHUNKS;
    float acc[8] = {0, 0, 0, 0, 0, 0, 0, 0};
    const float* xp = x + ((size_t)b * Sc + (size_t)sc * SS) * Hc;
    for (int s = 0; s < SS; ++s) {
#pragma unroll
        for (int hh = 0; hh < 8; ++hh)
            acc[hh] += xp[(size_t)s * Hc + tid + hh * 256];
    }
#pragma unroll
    for (int hh = 0; hh < 8; ++hh)
        g_part[((size_t)sc * Bc + b) * Hc + tid + hh * 256] = acc[hh];
}

__global__ void mean_reduce_kernel() {
    const int i = blockIdx.x * 256 + threadIdx.x;
    float s = 0.f;
#pragma unroll
    for (int sc = 0; sc < SCHUNKS; ++sc) s += g_part[(size_t)sc * Bc * Hc + i];
    g_xmean[i] = s * (1.0f / (float)Sc);
}

__global__ void wc_kernel(const float* __restrict__ W, const float* __restrict__ bw) {
    const int gw = (blockIdx.x * blockDim.x + threadIdx.x) >> 5;
    const int lane = threadIdx.x & 31;
    if (gw >= Bc * Hc) return;
    const int b = gw >> 11, i = gw & (Hc - 1);
    const float4* wr = (const float4*)(W + (size_t)i * Hc);
    const float4* xm = (const float4*)(g_xmean + (size_t)b * Hc);
    float s = 0.f;
    for (int k = lane; k < Hc / 4; k += 32) {
        float4 w4 = wr[k], x4 = xm[k];
        s += w4.x * x4.x + w4.y * x4.y + w4.z * x4.z + w4.w * x4.w;
    }
#pragma unroll
    for (int d = 16; d >= 1; d >>= 1) s += __shfl_xor_sync(0xffffffffu, s, d);
    if (lane == 0) g_wc[gw] = s + bw[i];
}

__global__ void newmem_kernel(const float* __restrict__ mem, float* __restrict__ outnm) {
    const size_t idx = (size_t)blockIdx.x * 256 + threadIdx.x;
    const int h4 = (int)(idx & (Hc / 4 - 1));
    const size_t rest = idx >> 9;
    const int m = (int)(rest & (Mslots - 1));
    const int b = (int)(rest >> 8);
    float4 mv = *(const float4*)(mem + (size_t)m * Hc + h4 * 4);
    float4 wv = *(const float4*)(g_wc + (size_t)b * Hc + h4 * 4);
    ((float4*)outnm)[idx] = make_float4(0.9f * mv.x + 0.1f * wv.x, 0.9f * mv.y + 0.1f * wv.y,
                                        0.9f * mv.z + 0.1f * wv.z, 0.9f * mv.w + 0.1f * wv.w);
}

// ======================= launch (fork-join: write path overlaps fused) =======================
extern "C" void kernel_launch(void* const* d_in, const int* in_sizes, int n_in,
                              void* d_out, int out_size) {
    const float* x   = (const float*)d_in[0];
    const float* mem = (const float*)d_in[1];
    const float* W   = (const float*)d_in[2];
    const float* bw  = (const float*)d_in[3];

    float* comb  = (float*)d_out;
    float* readm = comb + (size_t)NROWS * 2 * Hc;
    float* newm  = readm + (size_t)NROWS * Hc;

    // one-time resources (created on the first, non-capturing correctness call;
    // only capture-legal record/wait ops execute during graph capture)
    static cudaStream_t s_side = nullptr;
    static cudaEvent_t  e_fork = nullptr, e_join = nullptr;
    if (s_side == nullptr) {
        cudaStreamCreateWithFlags(&s_side, cudaStreamNonBlocking);
        cudaEventCreateWithFlags(&e_fork, cudaEventDisableTiming);
        cudaEventCreateWithFlags(&e_join, cudaEventDisableTiming);
    }

    cudaFuncSetAttribute(fused_mma_kernel,
                         cudaFuncAttributeMaxDynamicSharedMemorySize, DSMEM);

    // main stream: prep (fused depends on g_memF)
    prep_mem_kernel<<<(Mslots * Hc) / 256, 256>>>(mem);
    cudaEventRecord(e_fork, 0);

    // side stream: independent write path, overlapped with fused kernel
    cudaStreamWaitEvent(s_side, e_fork, 0);
    mean_part_kernel<<<dim3(SCHUNKS, Bc), 256, 0, s_side>>>(x);
    mean_reduce_kernel<<<(Bc * Hc) / 256, 256, 0, s_side>>>();
    wc_kernel<<<(Bc * Hc * 32) / 256, 256, 0, s_side>>>(W, bw);
    newmem_kernel<<<(Bc * Mslots * Hc / 4) / 256, 256, 0, s_side>>>(mem, newm);
    cudaEventRecord(e_join, s_side);

    // main stream: fused kernel runs concurrently with the side stream
    fused_mma_kernel<<<NROWS / BRr, THREADS, DSMEM>>>(x, mem, comb, readm);
    cudaStreamWaitEvent(0, e_join, 0);
}